// round 2
// baseline (speedup 1.0000x reference)
#include <cuda_runtime.h>
#include <math.h>

// Problem constants (fixed by setup_inputs)
#define NBATCH 2
#define NPB_NODES 20000           // nodes per batch
#define BN (NBATCH * NPB_NODES)   // 40000 total nodes
#define KNB 32                    // max neighbors
#define H 128                     // hidden dim (= F)
#define C 40                      // classes
#define NPB 32                    // nodes per block iteration
#define THREADS 256

// Ping-pong hidden-state buffers (scratch via __device__ globals; no runtime alloc)
__device__ float g_h0[BN * H];
__device__ float g_h1[BN * H];

// ---------------------------------------------------------------------------
// Embed: h = (X @ W_embed) / rowsum(X)
// ---------------------------------------------------------------------------
extern "C" __global__ void __launch_bounds__(THREADS)
embed_kernel(const float* __restrict__ X, const float* __restrict__ W,
             float* __restrict__ out)
{
    extern __shared__ float sm[];
    float* Wsh  = sm;                  // 16384 floats
    float* xs   = sm + 16384;          // 32*128
    float* invs = xs + NPB * H;        // 32

    const int tid  = threadIdx.x;
    const int lane = tid & 31;
    const int w    = tid >> 5;         // warp id = node-set id (0..7)

    for (int i = tid; i < H * H; i += THREADS) Wsh[i] = W[i];

    const float4* X4 = (const float4*)X;

    for (int base = blockIdx.x * NPB; base < BN; base += gridDim.x * NPB) {
        #pragma unroll
        for (int j = 0; j < 4; j++) {
            int n    = w * 4 + j;
            int node = base + n;
            float4 v = X4[node * 32 + lane];
            ((float4*)(xs + n * H))[lane] = v;
            float s = v.x + v.y + v.z + v.w;
            #pragma unroll
            for (int o = 16; o; o >>= 1) s += __shfl_xor_sync(0xffffffffu, s, o);
            if (lane == 0) invs[n] = 1.0f / s;
        }
        __syncthreads();  // also covers initial Wsh load

        float4 acc[4];
        #pragma unroll
        for (int j = 0; j < 4; j++) acc[j] = make_float4(0.f, 0.f, 0.f, 0.f);

        #pragma unroll 4
        for (int f = 0; f < H; f++) {
            float4 w4 = ((const float4*)(Wsh + f * H))[lane];
            #pragma unroll
            for (int j = 0; j < 4; j++) {
                float a = xs[(w * 4 + j) * H + f];
                acc[j].x += a * w4.x;
                acc[j].y += a * w4.y;
                acc[j].z += a * w4.z;
                acc[j].w += a * w4.w;
            }
        }
        #pragma unroll
        for (int j = 0; j < 4; j++) {
            int n = w * 4 + j;
            int node = base + n;
            float inv = invs[n];
            float4 o = make_float4(acc[j].x * inv, acc[j].y * inv,
                                   acc[j].z * inv, acc[j].w * inv);
            ((float4*)out)[node * 32 + lane] = o;
        }
        __syncthreads();
    }
}

// ---------------------------------------------------------------------------
// GCN layer: h_out = relu( (sum_all_K(h_in[nbr]) / max(vlen,1)) @ W + h_in @ B )
// NOTE: reference sums ALL K=32 neighbors; valid_lens is ONLY the divisor.
// ---------------------------------------------------------------------------
extern "C" __global__ void __launch_bounds__(THREADS)
gcn_layer_kernel(const float* __restrict__ hin, float* __restrict__ hout,
                 const int* __restrict__ nbr, const int* __restrict__ vlen,
                 const float* __restrict__ Wp, const float* __restrict__ Bp)
{
    extern __shared__ float sm[];
    float* Wsh = sm;                   // 16384
    float* Bsh = sm + 16384;           // 16384
    float* agg = Bsh + 16384;          // 32*128
    float* hss = agg + NPB * H;        // 32*128

    const int tid  = threadIdx.x;
    const int lane = tid & 31;
    const int w    = tid >> 5;

    for (int i = tid; i < H * H; i += THREADS) { Wsh[i] = Wp[i]; Bsh[i] = Bp[i]; }

    const float4* h4 = (const float4*)hin;

    for (int base = blockIdx.x * NPB; base < BN; base += gridDim.x * NPB) {
        // ---- Gather phase: warp w aggregates 4 nodes, ALL 32 neighbors ----
        #pragma unroll
        for (int j = 0; j < 4; j++) {
            int n    = w * 4 + j;
            int node = base + n;
            int boff = (node >= NPB_NODES) ? NPB_NODES : 0;  // batch offset
            int myi  = nbr[node * KNB + lane];               // one idx per lane
            int len  = vlen[node];
            float4 acc = make_float4(0.f, 0.f, 0.f, 0.f);
            #pragma unroll
            for (int k = 0; k < KNB; k++) {
                int idx = __shfl_sync(0xffffffffu, myi, k);
                float4 v = h4[(boff + idx) * 32 + lane];
                acc.x += v.x; acc.y += v.y; acc.z += v.z; acc.w += v.w;
            }
            float inv = 1.0f / (float)(len > 0 ? len : 1);
            acc.x *= inv; acc.y *= inv; acc.z *= inv; acc.w *= inv;
            ((float4*)(agg + n * H))[lane] = acc;
            ((float4*)(hss + n * H))[lane] = h4[node * 32 + lane];
        }
        __syncthreads();

        // ---- Matvec phase: 4 nodes x 4 dims per thread ----
        float4 acc[4];
        #pragma unroll
        for (int j = 0; j < 4; j++) acc[j] = make_float4(0.f, 0.f, 0.f, 0.f);

        #pragma unroll 4
        for (int f = 0; f < H; f++) {
            float4 w4 = ((const float4*)(Wsh + f * H))[lane];
            float4 b4 = ((const float4*)(Bsh + f * H))[lane];
            #pragma unroll
            for (int j = 0; j < 4; j++) {
                float a = agg[(w * 4 + j) * H + f];
                float s = hss[(w * 4 + j) * H + f];
                acc[j].x += a * w4.x + s * b4.x;
                acc[j].y += a * w4.y + s * b4.y;
                acc[j].z += a * w4.z + s * b4.z;
                acc[j].w += a * w4.w + s * b4.w;
            }
        }
        #pragma unroll
        for (int j = 0; j < 4; j++) {
            int node = base + w * 4 + j;
            float4 o = make_float4(fmaxf(acc[j].x, 0.f), fmaxf(acc[j].y, 0.f),
                                   fmaxf(acc[j].z, 0.f), fmaxf(acc[j].w, 0.f));
            ((float4*)hout)[node * 32 + lane] = o;
        }
        __syncthreads();
    }
}

// ---------------------------------------------------------------------------
// Classifier: z = relu(h@W1+b1); logits = z@W2+b2; softmax -> out [BN, 40]
// ---------------------------------------------------------------------------
extern "C" __global__ void __launch_bounds__(THREADS)
classifier_kernel(const float* __restrict__ hin,
                  const float* __restrict__ W1, const float* __restrict__ b1,
                  const float* __restrict__ W2, const float* __restrict__ b2,
                  float* __restrict__ out)
{
    extern __shared__ float sm[];
    float* W1sh = sm;                    // 16384
    float* W2sh = W1sh + 16384;          // 128*40 = 5120
    float* b1sh = W2sh + H * C;          // 128
    float* b2sh = b1sh + H;              // 40
    float* hsh  = b2sh + C;              // 32*128
    float* zsh  = hsh + NPB * H;         // 32*128

    const int tid  = threadIdx.x;
    const int lane = tid & 31;
    const int w    = tid >> 5;

    for (int i = tid; i < H * H; i += THREADS) W1sh[i] = W1[i];
    for (int i = tid; i < H * C; i += THREADS) W2sh[i] = W2[i];
    if (tid < H) b1sh[tid] = b1[tid];
    if (tid < C) b2sh[tid] = b2[tid];

    const float4* h4 = (const float4*)hin;

    for (int base = blockIdx.x * NPB; base < BN; base += gridDim.x * NPB) {
        #pragma unroll
        for (int j = 0; j < 4; j++) {
            int n = w * 4 + j;
            ((float4*)(hsh + n * H))[lane] = h4[(base + n) * 32 + lane];
        }
        __syncthreads();

        // z = relu(h @ W1 + b1)
        float4 acc[4];
        #pragma unroll
        for (int j = 0; j < 4; j++) acc[j] = make_float4(0.f, 0.f, 0.f, 0.f);
        #pragma unroll 4
        for (int f = 0; f < H; f++) {
            float4 w4 = ((const float4*)(W1sh + f * H))[lane];
            #pragma unroll
            for (int j = 0; j < 4; j++) {
                float a = hsh[(w * 4 + j) * H + f];
                acc[j].x += a * w4.x;
                acc[j].y += a * w4.y;
                acc[j].z += a * w4.z;
                acc[j].w += a * w4.w;
            }
        }
        float4 bb = ((const float4*)b1sh)[lane];
        #pragma unroll
        for (int j = 0; j < 4; j++) {
            int n = w * 4 + j;
            float4 z = make_float4(fmaxf(acc[j].x + bb.x, 0.f),
                                   fmaxf(acc[j].y + bb.y, 0.f),
                                   fmaxf(acc[j].z + bb.z, 0.f),
                                   fmaxf(acc[j].w + bb.w, 0.f));
            ((float4*)(zsh + n * H))[lane] = z;
        }
        __syncthreads();

        // Logits + softmax: warp w handles its 4 nodes
        int c2 = 32 + (lane & 7);
        bool has2 = (lane < 8);
        #pragma unroll
        for (int j = 0; j < 4; j++) {
            int n = w * 4 + j;
            int node = base + n;
            float l1 = b2sh[lane];
            float l2 = b2sh[c2];
            #pragma unroll 4
            for (int f = 0; f < H; f++) {
                float zv = zsh[n * H + f];
                l1 += zv * W2sh[f * C + lane];
                l2 += zv * W2sh[f * C + c2];
            }
            float m = fmaxf(l1, has2 ? l2 : -INFINITY);
            #pragma unroll
            for (int o = 16; o; o >>= 1) m = fmaxf(m, __shfl_xor_sync(0xffffffffu, m, o));
            float e1 = __expf(l1 - m);
            float e2 = has2 ? __expf(l2 - m) : 0.f;
            float s = e1 + e2;
            #pragma unroll
            for (int o = 16; o; o >>= 1) s += __shfl_xor_sync(0xffffffffu, s, o);
            float invs = 1.0f / s;
            out[node * C + lane] = e1 * invs;
            if (has2) out[node * C + c2] = e2 * invs;
        }
        __syncthreads();
    }
}

// ---------------------------------------------------------------------------
// Launch
// ---------------------------------------------------------------------------
#define EMBED_SMEM  ((16384 + NPB * H + 32) * 4)
#define LAYER_SMEM  ((2 * 16384 + 2 * NPB * H) * 4)
#define CLS_SMEM    ((16384 + H * C + H + C + 2 * NPB * H) * 4)

extern "C" void kernel_launch(void* const* d_in, const int* in_sizes, int n_in,
                              void* d_out, int out_size)
{
    const float* X    = (const float*)d_in[0];
    const int*   nbr  = (const int*)d_in[1];
    const int*   vlen = (const int*)d_in[2];
    const float* We   = (const float*)d_in[3];
    const float* gW   = (const float*)d_in[4];
    const float* gB   = (const float*)d_in[5];
    const float* W1   = (const float*)d_in[6];
    const float* b1   = (const float*)d_in[7];
    const float* W2   = (const float*)d_in[8];
    const float* b2   = (const float*)d_in[9];
    float* out = (float*)d_out;

    (void)in_sizes; (void)n_in; (void)out_size;

    cudaFuncSetAttribute(embed_kernel,      cudaFuncAttributeMaxDynamicSharedMemorySize, EMBED_SMEM);
    cudaFuncSetAttribute(gcn_layer_kernel,  cudaFuncAttributeMaxDynamicSharedMemorySize, LAYER_SMEM);
    cudaFuncSetAttribute(classifier_kernel, cudaFuncAttributeMaxDynamicSharedMemorySize, CLS_SMEM);

    float* h0 = nullptr;
    float* h1 = nullptr;
    cudaGetSymbolAddress((void**)&h0, g_h0);
    cudaGetSymbolAddress((void**)&h1, g_h1);

    embed_kernel<<<296, THREADS, EMBED_SMEM>>>(X, We, h0);

    gcn_layer_kernel<<<148, THREADS, LAYER_SMEM>>>(h0, h1, nbr, vlen,
                                                   gW + 0 * H * H, gB + 0 * H * H);
    gcn_layer_kernel<<<148, THREADS, LAYER_SMEM>>>(h1, h0, nbr, vlen,
                                                   gW + 1 * H * H, gB + 1 * H * H);
    gcn_layer_kernel<<<148, THREADS, LAYER_SMEM>>>(h0, h1, nbr, vlen,
                                                   gW + 2 * H * H, gB + 2 * H * H);

    classifier_kernel<<<148, THREADS, CLS_SMEM>>>(h1, W1, b1, W2, b2, out);
}

// round 3
// speedup vs baseline: 1.3641x; 1.3641x over previous
#include <cuda_runtime.h>
#include <math.h>

// Problem constants (fixed by setup_inputs)
#define NBATCH 2
#define NPB_NODES 20000           // nodes per batch
#define BN (NBATCH * NPB_NODES)   // 40000 total nodes
#define KNB 32                    // max neighbors
#define H 128                     // hidden dim (= F)
#define C 40                      // classes
#define THREADS 256
#define NWARPS 8
#define GRID_GCN 148
#define TOTAL_WARPS (GRID_GCN * NWARPS)   // 1184
#define NPW 8                      // nodes per warp (gcn/cls)
#define NGROUPS (BN / NPW)         // 5000

// Ping-pong hidden-state buffers
__device__ float g_h0[BN * H];
__device__ float g_h1[BN * H];

// packed f32x2 helpers
#define FMA2(acc, a, b) asm("fma.rn.f32x2 %0, %1, %2, %0;" : "+l"(acc) : "l"(a), "l"(b))
#define PACK2(d, s)     asm("mov.b64 %0, {%1, %1};" : "=l"(d) : "f"(s))
#define UNPACK2(lo, hi, s) asm("mov.b64 {%0, %1}, %2;" : "=f"(lo), "=f"(hi) : "l"(s))

// ---------------------------------------------------------------------------
// Embed: h = (X @ W_embed) / rowsum(X).  Warp-independent (4 nodes/warp tile).
// ---------------------------------------------------------------------------
extern "C" __global__ void __launch_bounds__(THREADS)
embed_kernel(const float* __restrict__ X, const float* __restrict__ W,
             float* __restrict__ out)
{
    extern __shared__ float sm[];
    float* Wsh = sm;                  // 16384 floats
    float* xs  = sm + 16384;          // 32*128 (per-warp 4 rows)

    const int tid  = threadIdx.x;
    const int lane = tid & 31;
    const int w    = tid >> 5;

    for (int i = tid; i < H * H; i += THREADS) Wsh[i] = W[i];
    __syncthreads();

    float* xsw = xs + (w * 4) * H;
    const float4* X4 = (const float4*)X;

    const int gw = blockIdx.x * NWARPS + w;
    const int nwarps_total = gridDim.x * NWARPS;
    for (int g = gw; g < BN / 4; g += nwarps_total) {
        const int base = g * 4;
        float inv[4];
        #pragma unroll
        for (int j = 0; j < 4; j++) {
            float4 v = X4[(base + j) * 32 + lane];
            ((float4*)(xsw + j * H))[lane] = v;
            float s = v.x + v.y + v.z + v.w;
            #pragma unroll
            for (int o = 16; o; o >>= 1) s += __shfl_xor_sync(0xffffffffu, s, o);
            inv[j] = 1.0f / s;
        }
        __syncwarp();

        unsigned long long axy[4], azw[4];
        #pragma unroll
        for (int j = 0; j < 4; j++) { axy[j] = 0ull; azw[j] = 0ull; }

        #pragma unroll 2
        for (int f0 = 0; f0 < H; f0 += 4) {
            ulonglong2 wv[4];
            #pragma unroll
            for (int q = 0; q < 4; q++)
                wv[q] = ((const ulonglong2*)(Wsh + (f0 + q) * H))[lane];
            #pragma unroll
            for (int j = 0; j < 4; j++) {
                float4 av = *(const float4*)(xsw + j * H + f0);
                unsigned long long aa;
                PACK2(aa, av.x); FMA2(axy[j], aa, wv[0].x); FMA2(azw[j], aa, wv[0].y);
                PACK2(aa, av.y); FMA2(axy[j], aa, wv[1].x); FMA2(azw[j], aa, wv[1].y);
                PACK2(aa, av.z); FMA2(axy[j], aa, wv[2].x); FMA2(azw[j], aa, wv[2].y);
                PACK2(aa, av.w); FMA2(axy[j], aa, wv[3].x); FMA2(azw[j], aa, wv[3].y);
            }
        }
        #pragma unroll
        for (int j = 0; j < 4; j++) {
            float x, y, z, u;
            UNPACK2(x, y, axy[j]);
            UNPACK2(z, u, azw[j]);
            float4 o = make_float4(x * inv[j], y * inv[j], z * inv[j], u * inv[j]);
            ((float4*)out)[(base + j) * 32 + lane] = o;
        }
        __syncwarp();
    }
}

// ---------------------------------------------------------------------------
// GCN layer: h_out = relu( (sum_K h_in[nbr]) / max(vlen,1) @ W + h_in @ B )
// Warp-independent: warp owns 8 nodes; gather + matvec pipeline via warp drift.
// ---------------------------------------------------------------------------
extern "C" __global__ void __launch_bounds__(THREADS, 1)
gcn_layer_kernel(const float* __restrict__ hin, float* __restrict__ hout,
                 const int* __restrict__ nbr, const int* __restrict__ vlen,
                 const float* __restrict__ Wp, const float* __restrict__ Bp)
{
    extern __shared__ float sm[];
    float* Wsh = sm;                   // 16384
    float* Bsh = sm + 16384;           // 16384
    float* agg = Bsh + 16384;          // 64*128
    float* hss = agg + 64 * H;         // 64*128

    const int tid  = threadIdx.x;
    const int lane = tid & 31;
    const int w    = tid >> 5;

    for (int i = tid; i < H * H; i += THREADS) { Wsh[i] = Wp[i]; Bsh[i] = Bp[i]; }
    __syncthreads();

    float* aggw = agg + (w * NPW) * H;
    float* hssw = hss + (w * NPW) * H;
    const float4* h4 = (const float4*)hin;

    const int gw = blockIdx.x * NWARPS + w;
    for (int g = gw; g < NGROUPS; g += TOTAL_WARPS) {
        const int base = g * NPW;                       // groups never straddle batches
        const int boff = (base >= NPB_NODES) ? NPB_NODES : 0;

        int myi[NPW];
        #pragma unroll
        for (int n = 0; n < NPW; n++) myi[n] = nbr[(base + n) * KNB + lane];

        #pragma unroll
        for (int n = 0; n < NPW; n++) {
            float4 a0 = make_float4(0.f, 0.f, 0.f, 0.f);
            float4 a1 = make_float4(0.f, 0.f, 0.f, 0.f);
            #pragma unroll
            for (int k = 0; k < 16; k++) {
                int i0 = __shfl_sync(0xffffffffu, myi[n], k);
                int i1 = __shfl_sync(0xffffffffu, myi[n], k + 16);
                float4 v0 = h4[(boff + i0) * 32 + lane];
                float4 v1 = h4[(boff + i1) * 32 + lane];
                a0.x += v0.x; a0.y += v0.y; a0.z += v0.z; a0.w += v0.w;
                a1.x += v1.x; a1.y += v1.y; a1.z += v1.z; a1.w += v1.w;
            }
            int len = vlen[base + n];
            float inv = 1.0f / (float)(len > 0 ? len : 1);
            float4 r = make_float4((a0.x + a1.x) * inv, (a0.y + a1.y) * inv,
                                   (a0.z + a1.z) * inv, (a0.w + a1.w) * inv);
            ((float4*)(aggw + n * H))[lane] = r;
            ((float4*)(hssw + n * H))[lane] = h4[(base + n) * 32 + lane];
        }
        __syncwarp();

        unsigned long long axy[NPW], azw[NPW];
        #pragma unroll
        for (int n = 0; n < NPW; n++) { axy[n] = 0ull; azw[n] = 0ull; }

        #pragma unroll 2
        for (int f0 = 0; f0 < H; f0 += 4) {
            ulonglong2 wv[4], bv[4];
            #pragma unroll
            for (int q = 0; q < 4; q++) {
                wv[q] = ((const ulonglong2*)(Wsh + (f0 + q) * H))[lane];
                bv[q] = ((const ulonglong2*)(Bsh + (f0 + q) * H))[lane];
            }
            #pragma unroll
            for (int n = 0; n < NPW; n++) {
                float4 av = *(const float4*)(aggw + n * H + f0);
                float4 sv = *(const float4*)(hssw + n * H + f0);
                unsigned long long aa, ss;
                PACK2(aa, av.x); PACK2(ss, sv.x);
                FMA2(axy[n], aa, wv[0].x); FMA2(axy[n], ss, bv[0].x);
                FMA2(azw[n], aa, wv[0].y); FMA2(azw[n], ss, bv[0].y);
                PACK2(aa, av.y); PACK2(ss, sv.y);
                FMA2(axy[n], aa, wv[1].x); FMA2(axy[n], ss, bv[1].x);
                FMA2(azw[n], aa, wv[1].y); FMA2(azw[n], ss, bv[1].y);
                PACK2(aa, av.z); PACK2(ss, sv.z);
                FMA2(axy[n], aa, wv[2].x); FMA2(axy[n], ss, bv[2].x);
                FMA2(azw[n], aa, wv[2].y); FMA2(azw[n], ss, bv[2].y);
                PACK2(aa, av.w); PACK2(ss, sv.w);
                FMA2(axy[n], aa, wv[3].x); FMA2(axy[n], ss, bv[3].x);
                FMA2(azw[n], aa, wv[3].y); FMA2(azw[n], ss, bv[3].y);
            }
        }

        #pragma unroll
        for (int n = 0; n < NPW; n++) {
            float x, y, z, u;
            UNPACK2(x, y, axy[n]);
            UNPACK2(z, u, azw[n]);
            float4 o = make_float4(fmaxf(x, 0.f), fmaxf(y, 0.f),
                                   fmaxf(z, 0.f), fmaxf(u, 0.f));
            ((float4*)hout)[(base + n) * 32 + lane] = o;
        }
        __syncwarp();
    }
}

// ---------------------------------------------------------------------------
// Classifier: z = relu(h@W1+b1); logits = z@W2+b2; softmax. Warp-independent.
// zsh is staged: first holds h rows, then overwritten with z rows.
// ---------------------------------------------------------------------------
extern "C" __global__ void __launch_bounds__(THREADS)
classifier_kernel(const float* __restrict__ hin,
                  const float* __restrict__ W1, const float* __restrict__ b1,
                  const float* __restrict__ W2, const float* __restrict__ b2,
                  float* __restrict__ out)
{
    extern __shared__ float sm[];
    float* W1sh = sm;                    // 16384
    float* W2sh = W1sh + 16384;          // 5120
    float* b1sh = W2sh + H * C;          // 128
    float* b2sh = b1sh + H;              // 40
    float* zsh  = b2sh + C;              // 64*128

    const int tid  = threadIdx.x;
    const int lane = tid & 31;
    const int w    = tid >> 5;

    for (int i = tid; i < H * H; i += THREADS) W1sh[i] = W1[i];
    for (int i = tid; i < H * C; i += THREADS) W2sh[i] = W2[i];
    if (tid < H) b1sh[tid] = b1[tid];
    if (tid < C) b2sh[tid] = b2[tid];
    __syncthreads();

    float* zshw = zsh + (w * NPW) * H;
    const float4* h4 = (const float4*)hin;

    const int c2 = 32 + (lane & 7);
    const bool has2 = (lane < 8);

    const int gw = blockIdx.x * NWARPS + w;
    for (int g = gw; g < NGROUPS; g += TOTAL_WARPS) {
        const int base = g * NPW;

        // stage h rows
        #pragma unroll
        for (int n = 0; n < NPW; n++)
            ((float4*)(zshw + n * H))[lane] = h4[(base + n) * 32 + lane];
        __syncwarp();

        // z = relu(h @ W1 + b1)
        unsigned long long axy[NPW], azw[NPW];
        #pragma unroll
        for (int n = 0; n < NPW; n++) { axy[n] = 0ull; azw[n] = 0ull; }

        #pragma unroll 2
        for (int f0 = 0; f0 < H; f0 += 4) {
            ulonglong2 wv[4];
            #pragma unroll
            for (int q = 0; q < 4; q++)
                wv[q] = ((const ulonglong2*)(W1sh + (f0 + q) * H))[lane];
            #pragma unroll
            for (int n = 0; n < NPW; n++) {
                float4 av = *(const float4*)(zshw + n * H + f0);
                unsigned long long aa;
                PACK2(aa, av.x); FMA2(axy[n], aa, wv[0].x); FMA2(azw[n], aa, wv[0].y);
                PACK2(aa, av.y); FMA2(axy[n], aa, wv[1].x); FMA2(azw[n], aa, wv[1].y);
                PACK2(aa, av.z); FMA2(axy[n], aa, wv[2].x); FMA2(azw[n], aa, wv[2].y);
                PACK2(aa, av.w); FMA2(axy[n], aa, wv[3].x); FMA2(azw[n], aa, wv[3].y);
            }
        }

        float4 bb = ((const float4*)b1sh)[lane];
        float4 zreg[NPW];
        #pragma unroll
        for (int n = 0; n < NPW; n++) {
            float x, y, z, u;
            UNPACK2(x, y, axy[n]);
            UNPACK2(z, u, azw[n]);
            zreg[n] = make_float4(fmaxf(x + bb.x, 0.f), fmaxf(y + bb.y, 0.f),
                                  fmaxf(z + bb.z, 0.f), fmaxf(u + bb.w, 0.f));
        }
        __syncwarp();   // everyone done reading h from zsh
        #pragma unroll
        for (int n = 0; n < NPW; n++)
            ((float4*)(zshw + n * H))[lane] = zreg[n];
        __syncwarp();

        // logits + softmax; interleaved accumulators across the 8 nodes
        float l1[NPW], l2[NPW];
        #pragma unroll
        for (int n = 0; n < NPW; n++) { l1[n] = b2sh[lane]; l2[n] = b2sh[c2]; }

        #pragma unroll 2
        for (int f0 = 0; f0 < H; f0 += 4) {
            float w2a[4], w2b[4];
            #pragma unroll
            for (int q = 0; q < 4; q++) {
                w2a[q] = W2sh[(f0 + q) * C + lane];
                w2b[q] = W2sh[(f0 + q) * C + c2];
            }
            #pragma unroll
            for (int n = 0; n < NPW; n++) {
                float4 zv = *(const float4*)(zshw + n * H + f0);
                l1[n] += zv.x * w2a[0] + zv.y * w2a[1];
                l1[n] += zv.z * w2a[2] + zv.w * w2a[3];
                l2[n] += zv.x * w2b[0] + zv.y * w2b[1];
                l2[n] += zv.z * w2b[2] + zv.w * w2b[3];
            }
        }

        #pragma unroll
        for (int n = 0; n < NPW; n++) {
            float m = fmaxf(l1[n], has2 ? l2[n] : -INFINITY);
            #pragma unroll
            for (int o = 16; o; o >>= 1) m = fmaxf(m, __shfl_xor_sync(0xffffffffu, m, o));
            float e1 = __expf(l1[n] - m);
            float e2 = has2 ? __expf(l2[n] - m) : 0.f;
            float s = e1 + e2;
            #pragma unroll
            for (int o = 16; o; o >>= 1) s += __shfl_xor_sync(0xffffffffu, s, o);
            float invs = 1.0f / s;
            out[(base + n) * C + lane] = e1 * invs;
            if (has2) out[(base + n) * C + c2] = e2 * invs;
        }
        __syncwarp();
    }
}

// ---------------------------------------------------------------------------
// Launch
// ---------------------------------------------------------------------------
#define EMBED_SMEM  ((16384 + 32 * H) * 4)
#define LAYER_SMEM  ((2 * 16384 + 2 * 64 * H) * 4)
#define CLS_SMEM    ((16384 + H * C + H + C + 64 * H) * 4)

extern "C" void kernel_launch(void* const* d_in, const int* in_sizes, int n_in,
                              void* d_out, int out_size)
{
    const float* X    = (const float*)d_in[0];
    const int*   nbr  = (const int*)d_in[1];
    const int*   vlen = (const int*)d_in[2];
    const float* We   = (const float*)d_in[3];
    const float* gW   = (const float*)d_in[4];
    const float* gB   = (const float*)d_in[5];
    const float* W1   = (const float*)d_in[6];
    const float* b1   = (const float*)d_in[7];
    const float* W2   = (const float*)d_in[8];
    const float* b2   = (const float*)d_in[9];
    float* out = (float*)d_out;

    (void)in_sizes; (void)n_in; (void)out_size;

    cudaFuncSetAttribute(embed_kernel,      cudaFuncAttributeMaxDynamicSharedMemorySize, EMBED_SMEM);
    cudaFuncSetAttribute(gcn_layer_kernel,  cudaFuncAttributeMaxDynamicSharedMemorySize, LAYER_SMEM);
    cudaFuncSetAttribute(classifier_kernel, cudaFuncAttributeMaxDynamicSharedMemorySize, CLS_SMEM);

    float* h0 = nullptr;
    float* h1 = nullptr;
    cudaGetSymbolAddress((void**)&h0, g_h0);
    cudaGetSymbolAddress((void**)&h1, g_h1);

    embed_kernel<<<296, THREADS, EMBED_SMEM>>>(X, We, h0);

    gcn_layer_kernel<<<GRID_GCN, THREADS, LAYER_SMEM>>>(h0, h1, nbr, vlen,
                                                        gW + 0 * H * H, gB + 0 * H * H);
    gcn_layer_kernel<<<GRID_GCN, THREADS, LAYER_SMEM>>>(h1, h0, nbr, vlen,
                                                        gW + 1 * H * H, gB + 1 * H * H);
    gcn_layer_kernel<<<GRID_GCN, THREADS, LAYER_SMEM>>>(h0, h1, nbr, vlen,
                                                        gW + 2 * H * H, gB + 2 * H * H);

    classifier_kernel<<<GRID_GCN, THREADS, CLS_SMEM>>>(h1, W1, b1, W2, b2, out);
}

// round 8
// speedup vs baseline: 1.5128x; 1.1090x over previous
#include <cuda_runtime.h>
#include <math.h>

// Problem constants (fixed by setup_inputs)
#define NBATCH 2
#define NPB_NODES 20000           // nodes per batch
#define BN (NBATCH * NPB_NODES)   // 40000 total nodes
#define KNB 32                    // max neighbors
#define H 128                     // hidden dim (= F)
#define C 40                      // classes
#define NPW 8                     // nodes per warp (gcn/cls)
#define NGROUPS (BN / NPW)        // 5000

#define THREADS_EMB 256
#define THREADS_GCN 384
#define NWARPS_GCN  12
#define THREADS_CLS 512
#define NWARPS_CLS  16
#define GRID_GCN 148
#define TOTAL_WARPS_GCN (GRID_GCN * NWARPS_GCN)   // 1776
#define TOTAL_WARPS_CLS (GRID_GCN * NWARPS_CLS)   // 2368

// Ping-pong hidden-state buffers
__device__ float g_h0[BN * H];
__device__ float g_h1[BN * H];

// packed f32x2 helpers
#define FMA2(acc, a, b) asm("fma.rn.f32x2 %0, %1, %2, %0;" : "+l"(acc) : "l"(a), "l"(b))
#define PACK2(d, s)     asm("mov.b64 %0, {%1, %1};" : "=l"(d) : "f"(s))
#define UNPACK2(lo, hi, s) asm("mov.b64 {%0, %1}, %2;" : "=f"(lo), "=f"(hi) : "l"(s))

// ---------------------------------------------------------------------------
// Embed: h = (X @ W_embed) / rowsum(X).  Warp-independent (4 nodes/warp tile).
// ---------------------------------------------------------------------------
extern "C" __global__ void __launch_bounds__(THREADS_EMB)
embed_kernel(const float* __restrict__ X, const float* __restrict__ W,
             float* __restrict__ out)
{
    extern __shared__ float sm[];
    float* Wsh = sm;                  // 16384 floats
    float* xs  = sm + 16384;          // 32*128 (per-warp 4 rows)

    const int tid  = threadIdx.x;
    const int lane = tid & 31;
    const int w    = tid >> 5;

    for (int i = tid; i < H * H; i += THREADS_EMB) Wsh[i] = W[i];
    __syncthreads();

    float* xsw = xs + (w * 4) * H;
    const float4* X4 = (const float4*)X;

    const int gw = blockIdx.x * (THREADS_EMB / 32) + w;
    const int nwarps_total = gridDim.x * (THREADS_EMB / 32);
    for (int g = gw; g < BN / 4; g += nwarps_total) {
        const int base = g * 4;
        float inv[4];
        #pragma unroll
        for (int j = 0; j < 4; j++) {
            float4 v = X4[(base + j) * 32 + lane];
            ((float4*)(xsw + j * H))[lane] = v;
            float s = v.x + v.y + v.z + v.w;
            #pragma unroll
            for (int o = 16; o; o >>= 1) s += __shfl_xor_sync(0xffffffffu, s, o);
            inv[j] = 1.0f / s;
        }
        __syncwarp();

        unsigned long long axy[4], azw[4];
        #pragma unroll
        for (int j = 0; j < 4; j++) { axy[j] = 0ull; azw[j] = 0ull; }

        #pragma unroll 2
        for (int f0 = 0; f0 < H; f0 += 4) {
            ulonglong2 wv[4];
            #pragma unroll
            for (int q = 0; q < 4; q++)
                wv[q] = ((const ulonglong2*)(Wsh + (f0 + q) * H))[lane];
            #pragma unroll
            for (int j = 0; j < 4; j++) {
                float4 av = *(const float4*)(xsw + j * H + f0);
                unsigned long long aa;
                PACK2(aa, av.x); FMA2(axy[j], aa, wv[0].x); FMA2(azw[j], aa, wv[0].y);
                PACK2(aa, av.y); FMA2(axy[j], aa, wv[1].x); FMA2(azw[j], aa, wv[1].y);
                PACK2(aa, av.z); FMA2(axy[j], aa, wv[2].x); FMA2(azw[j], aa, wv[2].y);
                PACK2(aa, av.w); FMA2(axy[j], aa, wv[3].x); FMA2(azw[j], aa, wv[3].y);
            }
        }
        #pragma unroll
        for (int j = 0; j < 4; j++) {
            float x, y, z, u;
            UNPACK2(x, y, axy[j]);
            UNPACK2(z, u, azw[j]);
            float4 o = make_float4(x * inv[j], y * inv[j], z * inv[j], u * inv[j]);
            ((float4*)out)[(base + j) * 32 + lane] = o;
        }
        __syncwarp();
    }
}

// ---------------------------------------------------------------------------
// GCN layer: h_out = relu( (sum_K h_in[nbr]) / max(vlen,1) @ W + h_in @ B )
// 12 warps/CTA; warp owns 8 nodes; gather/matvec overlap via warp drift.
// smem: 128KB weights + 12*8KB staging = 224KB (opt-in)
// ---------------------------------------------------------------------------
extern "C" __global__ void __launch_bounds__(THREADS_GCN, 1)
gcn_layer_kernel(const float* __restrict__ hin, float* __restrict__ hout,
                 const int* __restrict__ nbr, const int* __restrict__ vlen,
                 const float* __restrict__ Wp, const float* __restrict__ Bp)
{
    extern __shared__ float sm[];
    float* Wsh = sm;                          // 16384
    float* Bsh = sm + 16384;                  // 16384
    float* agg = Bsh + 16384;                 // 96*128
    float* hss = agg + NWARPS_GCN * NPW * H;  // 96*128

    const int tid  = threadIdx.x;
    const int lane = tid & 31;
    const int w    = tid >> 5;

    for (int i = tid; i < H * H; i += THREADS_GCN) { Wsh[i] = Wp[i]; Bsh[i] = Bp[i]; }
    __syncthreads();

    float* aggw = agg + (w * NPW) * H;
    float* hssw = hss + (w * NPW) * H;
    const float4* h4 = (const float4*)hin;

    const int gw = blockIdx.x * NWARPS_GCN + w;
    for (int g = gw; g < NGROUPS; g += TOTAL_WARPS_GCN) {
        const int base = g * NPW;                       // groups never straddle batches
        const int boff = (base >= NPB_NODES) ? NPB_NODES : 0;

        int myi[NPW];
        #pragma unroll
        for (int n = 0; n < NPW; n++) myi[n] = nbr[(base + n) * KNB + lane];
        int mylen = (lane < NPW) ? vlen[base + lane] : 1;

        #pragma unroll
        for (int n = 0; n < NPW; n++) {
            float4 a0 = make_float4(0.f, 0.f, 0.f, 0.f);
            float4 a1 = make_float4(0.f, 0.f, 0.f, 0.f);
            #pragma unroll
            for (int k = 0; k < 16; k++) {
                int i0 = __shfl_sync(0xffffffffu, myi[n], k);
                int i1 = __shfl_sync(0xffffffffu, myi[n], k + 16);
                float4 v0 = h4[(boff + i0) * 32 + lane];
                float4 v1 = h4[(boff + i1) * 32 + lane];
                a0.x += v0.x; a0.y += v0.y; a0.z += v0.z; a0.w += v0.w;
                a1.x += v1.x; a1.y += v1.y; a1.z += v1.z; a1.w += v1.w;
            }
            int len = __shfl_sync(0xffffffffu, mylen, n);
            float inv = 1.0f / (float)(len > 0 ? len : 1);
            float4 r = make_float4((a0.x + a1.x) * inv, (a0.y + a1.y) * inv,
                                   (a0.z + a1.z) * inv, (a0.w + a1.w) * inv);
            ((float4*)(aggw + n * H))[lane] = r;
            ((float4*)(hssw + n * H))[lane] = h4[(base + n) * 32 + lane];
        }
        __syncwarp();

        unsigned long long axy[NPW], azw[NPW];
        #pragma unroll
        for (int n = 0; n < NPW; n++) { axy[n] = 0ull; azw[n] = 0ull; }

        #pragma unroll 2
        for (int f0 = 0; f0 < H; f0 += 4) {
            ulonglong2 wv[4], bv[4];
            #pragma unroll
            for (int q = 0; q < 4; q++) {
                wv[q] = ((const ulonglong2*)(Wsh + (f0 + q) * H))[lane];
                bv[q] = ((const ulonglong2*)(Bsh + (f0 + q) * H))[lane];
            }
            #pragma unroll
            for (int n = 0; n < NPW; n++) {
                float4 av = *(const float4*)(aggw + n * H + f0);
                float4 sv = *(const float4*)(hssw + n * H + f0);
                unsigned long long aa, ss;
                PACK2(aa, av.x); PACK2(ss, sv.x);
                FMA2(axy[n], aa, wv[0].x); FMA2(axy[n], ss, bv[0].x);
                FMA2(azw[n], aa, wv[0].y); FMA2(azw[n], ss, bv[0].y);
                PACK2(aa, av.y); PACK2(ss, sv.y);
                FMA2(axy[n], aa, wv[1].x); FMA2(axy[n], ss, bv[1].x);
                FMA2(azw[n], aa, wv[1].y); FMA2(azw[n], ss, bv[1].y);
                PACK2(aa, av.z); PACK2(ss, sv.z);
                FMA2(axy[n], aa, wv[2].x); FMA2(axy[n], ss, bv[2].x);
                FMA2(azw[n], aa, wv[2].y); FMA2(azw[n], ss, bv[2].y);
                PACK2(aa, av.w); PACK2(ss, sv.w);
                FMA2(axy[n], aa, wv[3].x); FMA2(axy[n], ss, bv[3].x);
                FMA2(azw[n], aa, wv[3].y); FMA2(azw[n], ss, bv[3].y);
            }
        }

        #pragma unroll
        for (int n = 0; n < NPW; n++) {
            float x, y, z, u;
            UNPACK2(x, y, axy[n]);
            UNPACK2(z, u, azw[n]);
            float4 o = make_float4(fmaxf(x, 0.f), fmaxf(y, 0.f),
                                   fmaxf(z, 0.f), fmaxf(u, 0.f));
            ((float4*)hout)[(base + n) * 32 + lane] = o;
        }
        __syncwarp();
    }
}

// ---------------------------------------------------------------------------
// Classifier: z = relu(h@W1+b1); logits = z@W2+b2; softmax. 16 warps/CTA.
// ---------------------------------------------------------------------------
extern "C" __global__ void __launch_bounds__(THREADS_CLS)
classifier_kernel(const float* __restrict__ hin,
                  const float* __restrict__ W1, const float* __restrict__ b1,
                  const float* __restrict__ W2, const float* __restrict__ b2,
                  float* __restrict__ out)
{
    extern __shared__ float sm[];
    float* W1sh = sm;                    // 16384
    float* W2sh = W1sh + 16384;          // 5120
    float* b1sh = W2sh + H * C;          // 128
    float* b2sh = b1sh + H;              // 40
    float* zsh  = b2sh + C;              // 128*128

    const int tid  = threadIdx.x;
    const int lane = tid & 31;
    const int w    = tid >> 5;

    for (int i = tid; i < H * H; i += THREADS_CLS) W1sh[i] = W1[i];
    for (int i = tid; i < H * C; i += THREADS_CLS) W2sh[i] = W2[i];
    if (tid < H) b1sh[tid] = b1[tid];
    if (tid < C) b2sh[tid] = b2[tid];
    __syncthreads();

    float* zshw = zsh + (w * NPW) * H;
    const float4* h4 = (const float4*)hin;

    const int c2 = 32 + (lane & 7);
    const bool has2 = (lane < 8);

    const int gw = blockIdx.x * NWARPS_CLS + w;
    for (int g = gw; g < NGROUPS; g += TOTAL_WARPS_CLS) {
        const int base = g * NPW;

        // stage h rows
        #pragma unroll
        for (int n = 0; n < NPW; n++)
            ((float4*)(zshw + n * H))[lane] = h4[(base + n) * 32 + lane];
        __syncwarp();

        // z = relu(h @ W1 + b1)
        unsigned long long axy[NPW], azw[NPW];
        #pragma unroll
        for (int n = 0; n < NPW; n++) { axy[n] = 0ull; azw[n] = 0ull; }

        #pragma unroll 2
        for (int f0 = 0; f0 < H; f0 += 4) {
            ulonglong2 wv[4];
            #pragma unroll
            for (int q = 0; q < 4; q++)
                wv[q] = ((const ulonglong2*)(W1sh + (f0 + q) * H))[lane];
            #pragma unroll
            for (int n = 0; n < NPW; n++) {
                float4 av = *(const float4*)(zshw + n * H + f0);
                unsigned long long aa;
                PACK2(aa, av.x); FMA2(axy[n], aa, wv[0].x); FMA2(azw[n], aa, wv[0].y);
                PACK2(aa, av.y); FMA2(axy[n], aa, wv[1].x); FMA2(azw[n], aa, wv[1].y);
                PACK2(aa, av.z); FMA2(axy[n], aa, wv[2].x); FMA2(azw[n], aa, wv[2].y);
                PACK2(aa, av.w); FMA2(axy[n], aa, wv[3].x); FMA2(azw[n], aa, wv[3].y);
            }
        }

        float4 bb = ((const float4*)b1sh)[lane];
        float4 zreg[NPW];
        #pragma unroll
        for (int n = 0; n < NPW; n++) {
            float x, y, z, u;
            UNPACK2(x, y, axy[n]);
            UNPACK2(z, u, azw[n]);
            zreg[n] = make_float4(fmaxf(x + bb.x, 0.f), fmaxf(y + bb.y, 0.f),
                                  fmaxf(z + bb.z, 0.f), fmaxf(u + bb.w, 0.f));
        }
        __syncwarp();   // everyone done reading h from zsh
        #pragma unroll
        for (int n = 0; n < NPW; n++)
            ((float4*)(zshw + n * H))[lane] = zreg[n];
        __syncwarp();

        // logits + softmax; interleaved accumulators across the 8 nodes
        float l1[NPW], l2[NPW];
        #pragma unroll
        for (int n = 0; n < NPW; n++) { l1[n] = b2sh[lane]; l2[n] = b2sh[c2]; }

        #pragma unroll 2
        for (int f0 = 0; f0 < H; f0 += 4) {
            float w2a[4], w2b[4];
            #pragma unroll
            for (int q = 0; q < 4; q++) {
                w2a[q] = W2sh[(f0 + q) * C + lane];
                w2b[q] = W2sh[(f0 + q) * C + c2];
            }
            #pragma unroll
            for (int n = 0; n < NPW; n++) {
                float4 zv = *(const float4*)(zshw + n * H + f0);
                l1[n] += zv.x * w2a[0] + zv.y * w2a[1];
                l1[n] += zv.z * w2a[2] + zv.w * w2a[3];
                l2[n] += zv.x * w2b[0] + zv.y * w2b[1];
                l2[n] += zv.z * w2b[2] + zv.w * w2b[3];
            }
        }

        #pragma unroll
        for (int n = 0; n < NPW; n++) {
            float m = fmaxf(l1[n], has2 ? l2[n] : -INFINITY);
            #pragma unroll
            for (int o = 16; o; o >>= 1) m = fmaxf(m, __shfl_xor_sync(0xffffffffu, m, o));
            float e1 = __expf(l1[n] - m);
            float e2 = has2 ? __expf(l2[n] - m) : 0.f;
            float s = e1 + e2;
            #pragma unroll
            for (int o = 16; o; o >>= 1) s += __shfl_xor_sync(0xffffffffu, s, o);
            float invs = 1.0f / s;
            out[(base + n) * C + lane] = e1 * invs;
            if (has2) out[(base + n) * C + c2] = e2 * invs;
        }
        __syncwarp();
    }
}

// ---------------------------------------------------------------------------
// Launch
// ---------------------------------------------------------------------------
#define EMBED_SMEM  ((16384 + 32 * H) * 4)
#define LAYER_SMEM  ((2 * 16384 + 2 * NWARPS_GCN * NPW * H) * 4)   // 229376 B
#define CLS_SMEM    ((16384 + H * C + H + C + NWARPS_CLS * NPW * H) * 4)

extern "C" void kernel_launch(void* const* d_in, const int* in_sizes, int n_in,
                              void* d_out, int out_size)
{
    const float* X    = (const float*)d_in[0];
    const int*   nbr  = (const int*)d_in[1];
    const int*   vlen = (const int*)d_in[2];
    const float* We   = (const float*)d_in[3];
    const float* gW   = (const float*)d_in[4];
    const float* gB   = (const float*)d_in[5];
    const float* W1   = (const float*)d_in[6];
    const float* b1   = (const float*)d_in[7];
    const float* W2   = (const float*)d_in[8];
    const float* b2   = (const float*)d_in[9];
    float* out = (float*)d_out;

    (void)in_sizes; (void)n_in; (void)out_size;

    cudaFuncSetAttribute(embed_kernel,      cudaFuncAttributeMaxDynamicSharedMemorySize, EMBED_SMEM);
    cudaFuncSetAttribute(gcn_layer_kernel,  cudaFuncAttributeMaxDynamicSharedMemorySize, LAYER_SMEM);
    cudaFuncSetAttribute(classifier_kernel, cudaFuncAttributeMaxDynamicSharedMemorySize, CLS_SMEM);

    float* h0 = nullptr;
    float* h1 = nullptr;
    cudaGetSymbolAddress((void**)&h0, g_h0);
    cudaGetSymbolAddress((void**)&h1, g_h1);

    embed_kernel<<<296, THREADS_EMB, EMBED_SMEM>>>(X, We, h0);

    gcn_layer_kernel<<<GRID_GCN, THREADS_GCN, LAYER_SMEM>>>(h0, h1, nbr, vlen,
                                                            gW + 0 * H * H, gB + 0 * H * H);
    gcn_layer_kernel<<<GRID_GCN, THREADS_GCN, LAYER_SMEM>>>(h1, h0, nbr, vlen,
                                                            gW + 1 * H * H, gB + 1 * H * H);
    gcn_layer_kernel<<<GRID_GCN, THREADS_GCN, LAYER_SMEM>>>(h0, h1, nbr, vlen,
                                                            gW + 2 * H * H, gB + 2 * H * H);

    classifier_kernel<<<GRID_GCN, THREADS_CLS, CLS_SMEM>>>(h1, W1, b1, W2, b2, out);
}